// round 11
// baseline (speedup 1.0000x reference)
#include <cuda_runtime.h>

// metaCLF_20504173871859 — round 9: packed f32x2 (2 voxels/thread), pre-duplicated
// constant weights (LDCU.64 per weight), occupancy raised via 64-thread CTAs +
// __launch_bounds__(64,6) (12 warps/SM = 3/SMSP instead of 2/SMSP).
//
// Per-voxel math: out = sum_c x_c * (G3 @ relu(G2 @ relu(G1 @ kron3(enc(dx),enc(dy),enc(dz)))))_c
// Last two layers fused with the output dot (no filters[] materialization).

#define IN_CS 32
#define NVOX  (96 * 96 * 96)          // 884736 voxels per batch
#define HPAIR (NVOX / 2)              // voxel pairs per batch

typedef unsigned long long u64;

// Packed-weight constant layout (each weight stored duplicated (w,w)):
//   [0,32)      W1[i][0..1]  as i*2+{0,1}
//   [32,80)     W2[j][i]     as 32 + j*16+i
//   [80,944)    G1[c][j]     as 80 + c*27+j
//   [944,2992)  G2[k][c]     as 944 + k*32+c
//   [2992,5040) G3t[k][c] = G3[c][k]   as 2992 + k*32+c   (pre-transposed)
#define OFF_W1 0
#define OFF_W2 32
#define OFF_G1 80
#define OFF_G2 944
#define OFF_G3 2992
#define NPACK  5040

__constant__ float2 cPack[NPACK];          // 40,320 bytes
__device__  float2 g_packbuf[NPACK];       // prep scratch (no allocation)

// ---------------- packed f32x2 helpers ----------------
__device__ __forceinline__ u64 fma2(u64 a, u64 b, u64 c) {
    u64 d;
    asm("fma.rn.f32x2 %0, %1, %2, %3;" : "=l"(d) : "l"(a), "l"(b), "l"(c));
    return d;
}
__device__ __forceinline__ u64 mul2(u64 a, u64 b) {
    u64 d;
    asm("mul.rn.f32x2 %0, %1, %2;" : "=l"(d) : "l"(a), "l"(b));
    return d;
}
__device__ __forceinline__ u64 relu2(u64 v) {
    float lo, hi;
    asm("mov.b64 {%0, %1}, %2;" : "=f"(lo), "=f"(hi) : "l"(v));
    lo = fmaxf(lo, 0.0f);
    hi = fmaxf(hi, 0.0f);
    u64 r;
    asm("mov.b64 %0, {%1, %2};" : "=l"(r) : "f"(lo), "f"(hi));
    return r;
}
// duplicated weight pair from constant memory (compile-time index -> LDCU.64)
__device__ __forceinline__ u64 CP(int i) {
    return *reinterpret_cast<const u64*>(cPack + i);
}

// ---------------- prep: duplicate + reorder weights ----------------
__global__ void pack_weights_kernel(const float* __restrict__ W1,
                                    const float* __restrict__ W2,
                                    const float* __restrict__ G1,
                                    const float* __restrict__ G2,
                                    const float* __restrict__ G3)
{
    for (int i = threadIdx.x; i < NPACK; i += blockDim.x) {
        float w;
        if (i < OFF_W2) {                      // W1 [16][2], kept in row order
            w = W1[i - OFF_W1];
        } else if (i < OFF_G1) {               // W2 [3][16]
            w = W2[i - OFF_W2];
        } else if (i < OFF_G2) {               // G1 [32][27]
            w = G1[i - OFF_G1];
        } else if (i < OFF_G3) {               // G2 [64][32]
            w = G2[i - OFF_G2];
        } else {                               // G3t[k][c] = G3[c][k], G3 is [32][64]
            int t = i - OFF_G3;
            int k = t >> 5;                    // 0..63
            int c = t & 31;                    // 0..31
            w = G3[c * 64 + k];
        }
        g_packbuf[i] = make_float2(w, w);
    }
}

// ---------------- packed encode: W2 @ relu(W1 @ [a,b]) ----------------
__device__ __forceinline__ void encode2p(u64 a, u64 b, u64 o[3]) {
    u64 h[16];
#pragma unroll
    for (int i = 0; i < 16; ++i)
        h[i] = relu2(fma2(CP(OFF_W1 + 2 * i), a, mul2(CP(OFF_W1 + 2 * i + 1), b)));
#pragma unroll
    for (int j = 0; j < 3; ++j) {
        u64 s = mul2(CP(OFF_W2 + 16 * j), h[0]);
#pragma unroll
        for (int i = 1; i < 16; ++i)
            s = fma2(CP(OFF_W2 + 16 * j + i), h[i], s);
        o[j] = s;
    }
}

__global__ __launch_bounds__(64, 6)
void fused_filter2_kernel(const u64* __restrict__ x2,
                          const u64* __restrict__ d2,
                          u64* __restrict__ out2,
                          int npairs)
{
    int q = blockIdx.x * blockDim.x + threadIdx.x;
    if (q >= npairs) return;

    int b = q / HPAIR;                 // batch (0 or 1); pairs never straddle batches
    int p = q - b * HPAIR;

    const u64* xb = x2 + (size_t)b * IN_CS * HPAIR + p;   // channel stride HPAIR
    const u64* db = d2 + (size_t)b * 6     * HPAIR + p;

    // ---- encode the three directional pairs ----
    u64 xx[3], yy[3], zz[3];
    {
        u64 d0 = db[0];
        u64 d1 = db[(size_t)1 * HPAIR];
        u64 d2v = db[(size_t)2 * HPAIR];
        u64 d3 = db[(size_t)3 * HPAIR];
        u64 d4 = db[(size_t)4 * HPAIR];
        u64 d5 = db[(size_t)5 * HPAIR];
        encode2p(d0, d1, xx);
        encode2p(d2v, d3, yy);
        encode2p(d4, d5, zz);
    }

    // ---- enc = kron(kron(xx,yy),zz) : enc[i*9+j*3+k] ----
    u64 enc[27];
#pragma unroll
    for (int i = 0; i < 3; ++i) {
#pragma unroll
        for (int j = 0; j < 3; ++j) {
            u64 pij = mul2(xx[i], yy[j]);
#pragma unroll
            for (int k = 0; k < 3; ++k)
                enc[i * 9 + j * 3 + k] = mul2(pij, zz[k]);
        }
    }

    // ---- h1 = relu(G1 @ enc) [32] ----
    u64 h1[32];
#pragma unroll
    for (int c = 0; c < 32; ++c) {
        u64 s = mul2(CP(OFF_G1 + 27 * c), enc[0]);
#pragma unroll
        for (int j = 1; j < 27; ++j)
            s = fma2(CP(OFF_G1 + 27 * c + j), enc[j], s);
        h1[c] = relu2(s);
    }

    // ---- load x channels (8B coalesced, voxel pair contiguous) ----
    u64 xr[32];
#pragma unroll
    for (int c = 0; c < 32; ++c)
        xr[c] = xb[(size_t)c * HPAIR];

    // ---- fused G2/G3/output: out = sum_k relu(G2[k]·h1) * (G3t[k]·x) ----
    u64 acc = 0ull;   // packed (0.0f, 0.0f)
#pragma unroll 8
    for (int k = 0; k < 64; ++k) {
        u64 s2 = mul2(CP(OFF_G2 + 32 * k), h1[0]);
        u64 t  = mul2(CP(OFF_G3 + 32 * k), xr[0]);
#pragma unroll
        for (int c = 1; c < 32; ++c) {
            s2 = fma2(CP(OFF_G2 + 32 * k + c), h1[c], s2);
            t  = fma2(CP(OFF_G3 + 32 * k + c), xr[c], t);
        }
        acc = fma2(relu2(s2), t, acc);
    }

    out2[q] = acc;
}

extern "C" void kernel_launch(void* const* d_in, const int* in_sizes, int n_in,
                              void* d_out, int out_size)
{
    const float* x     = (const float*)d_in[0];
    const float* d_all = (const float*)d_in[1];

    // 1) duplicate/reorder weights into device scratch (single small block)
    pack_weights_kernel<<<1, 256>>>((const float*)d_in[2], (const float*)d_in[3],
                                    (const float*)d_in[4], (const float*)d_in[5],
                                    (const float*)d_in[6]);

    // 2) move scratch into constant bank (D2D memcpy node — graph-capturable)
    void* psrc = nullptr;
    cudaGetSymbolAddress(&psrc, g_packbuf);
    cudaMemcpyToSymbolAsync(cPack, psrc, sizeof(float2) * NPACK, 0,
                            cudaMemcpyDeviceToDevice, 0);

    // 3) main fused kernel, 2 voxels per thread, 64-thread CTAs for occupancy
    int npairs  = out_size / 2;        // 884,736
    int threads = 64;
    int blocks  = (npairs + threads - 1) / threads;
    fused_filter2_kernel<<<blocks, threads>>>((const u64*)x, (const u64*)d_all,
                                              (u64*)d_out, npairs);
}

// round 12
// speedup vs baseline: 1.0505x; 1.0505x over previous
#include <cuda_runtime.h>

// metaCLF_20504173871859 — round 12: R7 config (128 thr, minBlocks 2) + 16-byte
// constant weight loads (one LDCU.128 feeds TWO fma.rn.f32x2) to cut the
// weight-load issue count in half.
//
// Per-voxel math: out = sum_c x_c * (G3 @ relu(G2 @ relu(G1 @ kron3(enc(dx),enc(dy),enc(dz)))))_c
// 2 voxels per thread via packed f32x2; last two layers fused with output dot.

#define IN_CS 32
#define NVOX  (96 * 96 * 96)          // 884736 voxels per batch
#define HPAIR (NVOX / 2)              // voxel pairs per batch

typedef unsigned long long u64;

// Packed-weight constant layout (each weight duplicated (w,w) as float2).
// All row starts are EVEN indices so 16B (2-entry) loads are aligned.
//   [0,32)       W1[i][0..1]      at 2i, 2i+1
//   [32,80)      W2[j][i]         at 32 + 16j + i
//   [80,976)     G1[c][j]         at 80 + 28c + j   (rows padded 27->28, pad=0)
//   [976,3024)   G2[k][c]         at 976 + 32k + c
//   [3024,5072)  G3t[k][c]=G3[c][k] at 3024 + 32k + c   (pre-transposed)
#define OFF_W1 0
#define OFF_W2 32
#define OFF_G1 80
#define G1_STRIDE 28
#define OFF_G2 976
#define OFF_G3 3024
#define NPACK  5072

__constant__ float2 cPack[NPACK];          // 40,576 bytes
__device__  float2 g_packbuf[NPACK];       // prep scratch (no allocation)

// ---------------- packed f32x2 helpers ----------------
__device__ __forceinline__ u64 fma2(u64 a, u64 b, u64 c) {
    u64 d;
    asm("fma.rn.f32x2 %0, %1, %2, %3;" : "=l"(d) : "l"(a), "l"(b), "l"(c));
    return d;
}
__device__ __forceinline__ u64 mul2(u64 a, u64 b) {
    u64 d;
    asm("mul.rn.f32x2 %0, %1, %2;" : "=l"(d) : "l"(a), "l"(b));
    return d;
}
__device__ __forceinline__ u64 relu2(u64 v) {
    float lo, hi;
    asm("mov.b64 {%0, %1}, %2;" : "=f"(lo), "=f"(hi) : "l"(v));
    lo = fmaxf(lo, 0.0f);
    hi = fmaxf(hi, 0.0f);
    u64 r;
    asm("mov.b64 %0, {%1, %2};" : "=l"(r) : "f"(lo), "f"(hi));
    return r;
}
// one duplicated weight pair (8B) — compile-time even/odd index
__device__ __forceinline__ u64 CP(int i) {
    return *reinterpret_cast<const u64*>(cPack + i);
}
// TWO adjacent duplicated weight pairs (16B, LDCU.128) — index must be even
__device__ __forceinline__ ulonglong2 CP2(int i) {
    return *reinterpret_cast<const ulonglong2*>(cPack + i);
}

// ---------------- prep: duplicate + reorder weights ----------------
__global__ void pack_weights_kernel(const float* __restrict__ W1,
                                    const float* __restrict__ W2,
                                    const float* __restrict__ G1,
                                    const float* __restrict__ G2,
                                    const float* __restrict__ G3)
{
    for (int i = threadIdx.x; i < NPACK; i += blockDim.x) {
        float w = 0.0f;
        if (i < OFF_W2) {                       // W1 [16][2]
            w = W1[i - OFF_W1];
        } else if (i < OFF_G1) {                // W2 [3][16]
            w = W2[i - OFF_W2];
        } else if (i < OFF_G2) {                // G1 [32][27], padded rows of 28
            int t = i - OFF_G1;
            int c = t / G1_STRIDE;
            int j = t - c * G1_STRIDE;
            w = (j < 27) ? G1[c * 27 + j] : 0.0f;
        } else if (i < OFF_G3) {                // G2 [64][32]
            w = G2[i - OFF_G2];
        } else {                                // G3t[k][c] = G3[c][k], G3 is [32][64]
            int t = i - OFF_G3;
            int k = t >> 5;
            int c = t & 31;
            w = G3[c * 64 + k];
        }
        g_packbuf[i] = make_float2(w, w);
    }
}

// ---------------- packed encode: W2 @ relu(W1 @ [a,b]) ----------------
__device__ __forceinline__ void encode2p(u64 a, u64 b, u64 o[3]) {
    u64 h[16];
#pragma unroll
    for (int i = 0; i < 16; ++i) {
        ulonglong2 w = CP2(OFF_W1 + 2 * i);           // {W1[i][0], W1[i][1]}
        h[i] = relu2(fma2(w.x, a, mul2(w.y, b)));
    }
#pragma unroll
    for (int j = 0; j < 3; ++j) {
        ulonglong2 w0 = CP2(OFF_W2 + 16 * j);
        u64 s = fma2(w0.y, h[1], mul2(w0.x, h[0]));
#pragma unroll
        for (int i = 1; i < 8; ++i) {
            ulonglong2 w = CP2(OFF_W2 + 16 * j + 2 * i);
            s = fma2(w.x, h[2 * i], s);
            s = fma2(w.y, h[2 * i + 1], s);
        }
        o[j] = s;
    }
}

__global__ __launch_bounds__(128, 2)
void fused_filter2_kernel(const u64* __restrict__ x2,
                          const u64* __restrict__ d2,
                          u64* __restrict__ out2,
                          int npairs)
{
    int q = blockIdx.x * blockDim.x + threadIdx.x;
    if (q >= npairs) return;

    int b = q / HPAIR;                 // batch (0 or 1); pairs never straddle batches
    int p = q - b * HPAIR;

    const u64* xb = x2 + (size_t)b * IN_CS * HPAIR + p;   // channel stride HPAIR
    const u64* db = d2 + (size_t)b * 6     * HPAIR + p;

    // ---- encode the three directional pairs ----
    u64 xx[3], yy[3], zz[3];
    {
        u64 d0 = db[0];
        u64 d1 = db[(size_t)1 * HPAIR];
        u64 d2v = db[(size_t)2 * HPAIR];
        u64 d3 = db[(size_t)3 * HPAIR];
        u64 d4 = db[(size_t)4 * HPAIR];
        u64 d5 = db[(size_t)5 * HPAIR];
        encode2p(d0, d1, xx);
        encode2p(d2v, d3, yy);
        encode2p(d4, d5, zz);
    }

    // ---- enc = kron(kron(xx,yy),zz) : enc[i*9+j*3+k] ----
    u64 enc[27];
#pragma unroll
    for (int i = 0; i < 3; ++i) {
#pragma unroll
        for (int j = 0; j < 3; ++j) {
            u64 pij = mul2(xx[i], yy[j]);
#pragma unroll
            for (int k = 0; k < 3; ++k)
                enc[i * 9 + j * 3 + k] = mul2(pij, zz[k]);
        }
    }

    // ---- h1 = relu(G1 @ enc) [32], rows padded to 28 (13 wide pairs + 1) ----
    u64 h1[32];
#pragma unroll
    for (int c = 0; c < 32; ++c) {
        int base = OFF_G1 + G1_STRIDE * c;
        ulonglong2 w0 = CP2(base);
        u64 s = fma2(w0.y, enc[1], mul2(w0.x, enc[0]));
#pragma unroll
        for (int j = 1; j < 13; ++j) {
            ulonglong2 w = CP2(base + 2 * j);
            s = fma2(w.x, enc[2 * j], s);
            s = fma2(w.y, enc[2 * j + 1], s);
        }
        s = fma2(CP(base + 26), enc[26], s);
        h1[c] = relu2(s);
    }

    // ---- load x channels (8B coalesced, voxel pair contiguous) ----
    u64 xr[32];
#pragma unroll
    for (int c = 0; c < 32; ++c)
        xr[c] = xb[(size_t)c * HPAIR];

    // ---- fused G2/G3/output: out = sum_k relu(G2[k]·h1) * (G3t[k]·x) ----
    u64 acc = 0ull;   // packed (0.0f, 0.0f)
#pragma unroll 8
    for (int k = 0; k < 64; ++k) {
        int ba = OFF_G2 + 32 * k;
        int bb = OFF_G3 + 32 * k;
        ulonglong2 wa0 = CP2(ba);
        ulonglong2 wb0 = CP2(bb);
        u64 s2 = fma2(wa0.y, h1[1], mul2(wa0.x, h1[0]));
        u64 t  = fma2(wb0.y, xr[1], mul2(wb0.x, xr[0]));
#pragma unroll
        for (int c = 1; c < 16; ++c) {
            ulonglong2 wa = CP2(ba + 2 * c);
            ulonglong2 wb = CP2(bb + 2 * c);
            s2 = fma2(wa.x, h1[2 * c], s2);
            t  = fma2(wb.x, xr[2 * c], t);
            s2 = fma2(wa.y, h1[2 * c + 1], s2);
            t  = fma2(wb.y, xr[2 * c + 1], t);
        }
        acc = fma2(relu2(s2), t, acc);
    }

    out2[q] = acc;
}

extern "C" void kernel_launch(void* const* d_in, const int* in_sizes, int n_in,
                              void* d_out, int out_size)
{
    const float* x     = (const float*)d_in[0];
    const float* d_all = (const float*)d_in[1];

    // 1) duplicate/reorder weights into device scratch (single small block)
    pack_weights_kernel<<<1, 256>>>((const float*)d_in[2], (const float*)d_in[3],
                                    (const float*)d_in[4], (const float*)d_in[5],
                                    (const float*)d_in[6]);

    // 2) move scratch into constant bank (D2D memcpy node — graph-capturable)
    void* psrc = nullptr;
    cudaGetSymbolAddress(&psrc, g_packbuf);
    cudaMemcpyToSymbolAsync(cPack, psrc, sizeof(float2) * NPACK, 0,
                            cudaMemcpyDeviceToDevice, 0);

    // 3) main fused kernel, 2 voxels per thread (R7 launch config: 128 thr, 2 CTA/SM)
    int npairs  = out_size / 2;        // 884,736
    int threads = 128;
    int blocks  = (npairs + threads - 1) / threads;
    fused_filter2_kernel<<<blocks, threads>>>((const u64*)x, (const u64*)d_all,
                                              (u64*)d_out, npairs);
}

// round 14
// speedup vs baseline: 1.4456x; 1.3761x over previous
#include <cuda_runtime.h>

// metaCLF_20504173871859 — round 13: R7 base (packed f32x2, 2 voxels/thread,
// 8-byte LDCU weights, 128thr/2CTA) + DUAL-PORT weight sourcing:
// half the weight loads come from a SMEM mirror (LDS.64 -> GPR pool / LSU port),
// half from __constant__ (LDCU.64 -> UR pool / uniform port). Doubles the
// load-hoisting capacity that was capped by the 63-entry UR file.

#define IN_CS 32
#define NVOX  (96 * 96 * 96)          // 884736 voxels per batch
#define HPAIR (NVOX / 2)              // voxel pairs per batch

typedef unsigned long long u64;

// Packed-weight layout (each weight duplicated (w,w) as float2):
//   [0,32)      W1[i][0..1]  as i*2+{0,1}
//   [32,80)     W2[j][i]     as 32 + j*16+i
//   [80,944)    G1[c][j]     as 80 + c*27+j
//   [944,2992)  G2[k][c]     as 944 + k*32+c
//   [2992,5040) G3t[k][c] = G3[c][k]   as 2992 + k*32+c   (pre-transposed)
#define OFF_W1 0
#define OFF_W2 32
#define OFF_G1 80
#define OFF_G2 944
#define OFF_G3 2992
#define NPACK  5040

__constant__ float2 cPack[NPACK];          // 40,320 bytes
__device__  float2 g_packbuf[NPACK];       // prep scratch (no allocation)

// ---------------- packed f32x2 helpers ----------------
__device__ __forceinline__ u64 fma2(u64 a, u64 b, u64 c) {
    u64 d;
    asm("fma.rn.f32x2 %0, %1, %2, %3;" : "=l"(d) : "l"(a), "l"(b), "l"(c));
    return d;
}
__device__ __forceinline__ u64 mul2(u64 a, u64 b) {
    u64 d;
    asm("mul.rn.f32x2 %0, %1, %2;" : "=l"(d) : "l"(a), "l"(b));
    return d;
}
__device__ __forceinline__ u64 relu2(u64 v) {
    float lo, hi;
    asm("mov.b64 {%0, %1}, %2;" : "=f"(lo), "=f"(hi) : "l"(v));
    lo = fmaxf(lo, 0.0f);
    hi = fmaxf(hi, 0.0f);
    u64 r;
    asm("mov.b64 %0, {%1, %2};" : "=l"(r) : "f"(lo), "f"(hi));
    return r;
}
// duplicated weight pair from constant memory (compile-time index -> LDCU.64, UR pool)
__device__ __forceinline__ u64 CP(int i) {
    return *reinterpret_cast<const u64*>(cPack + i);
}
// duplicated weight pair from the SMEM mirror (LDS.64 broadcast, GPR pool)
__device__ __forceinline__ u64 SP(const float2* sw, int i) {
    return *reinterpret_cast<const u64*>(sw + i);
}

// ---------------- prep: duplicate + reorder weights ----------------
__global__ void pack_weights_kernel(const float* __restrict__ W1,
                                    const float* __restrict__ W2,
                                    const float* __restrict__ G1,
                                    const float* __restrict__ G2,
                                    const float* __restrict__ G3)
{
    for (int i = threadIdx.x; i < NPACK; i += blockDim.x) {
        float w;
        if (i < OFF_W2) {                      // W1 [16][2]
            w = W1[i - OFF_W1];
        } else if (i < OFF_G1) {               // W2 [3][16]
            w = W2[i - OFF_W2];
        } else if (i < OFF_G2) {               // G1 [32][27]
            w = G1[i - OFF_G1];
        } else if (i < OFF_G3) {               // G2 [64][32]
            w = G2[i - OFF_G2];
        } else {                               // G3t[k][c] = G3[c][k], G3 is [32][64]
            int t = i - OFF_G3;
            int k = t >> 5;
            int c = t & 31;
            w = G3[c * 64 + k];
        }
        g_packbuf[i] = make_float2(w, w);
    }
}

// ---------------- packed encode: W2 @ relu(W1 @ [a,b]) (constant port) ----
__device__ __forceinline__ void encode2p(u64 a, u64 b, u64 o[3]) {
    u64 h[16];
#pragma unroll
    for (int i = 0; i < 16; ++i)
        h[i] = relu2(fma2(CP(OFF_W1 + 2 * i), a, mul2(CP(OFF_W1 + 2 * i + 1), b)));
#pragma unroll
    for (int j = 0; j < 3; ++j) {
        u64 s = mul2(CP(OFF_W2 + 16 * j), h[0]);
#pragma unroll
        for (int i = 1; i < 16; ++i)
            s = fma2(CP(OFF_W2 + 16 * j + i), h[i], s);
        o[j] = s;
    }
}

__global__ __launch_bounds__(128, 2)
void fused_filter2_kernel(const u64* __restrict__ x2,
                          const u64* __restrict__ d2,
                          u64* __restrict__ out2,
                          int npairs)
{
    // SMEM mirror of the packed weights (LDS port relieves the UR/LDCU port)
    __shared__ float2 sPack[NPACK];
    for (int i = threadIdx.x; i < NPACK; i += blockDim.x)
        sPack[i] = g_packbuf[i];
    __syncthreads();

    int q = blockIdx.x * blockDim.x + threadIdx.x;
    if (q >= npairs) return;

    int b = q / HPAIR;                 // batch (0 or 1); pairs never straddle batches
    int p = q - b * HPAIR;

    const u64* xb = x2 + (size_t)b * IN_CS * HPAIR + p;   // channel stride HPAIR
    const u64* db = d2 + (size_t)b * 6     * HPAIR + p;

    // ---- encode the three directional pairs ----
    u64 xx[3], yy[3], zz[3];
    {
        u64 d0 = db[0];
        u64 d1 = db[(size_t)1 * HPAIR];
        u64 d2v = db[(size_t)2 * HPAIR];
        u64 d3 = db[(size_t)3 * HPAIR];
        u64 d4 = db[(size_t)4 * HPAIR];
        u64 d5 = db[(size_t)5 * HPAIR];
        encode2p(d0, d1, xx);
        encode2p(d2v, d3, yy);
        encode2p(d4, d5, zz);
    }

    // ---- enc = kron(kron(xx,yy),zz) : enc[i*9+j*3+k] ----
    u64 enc[27];
#pragma unroll
    for (int i = 0; i < 3; ++i) {
#pragma unroll
        for (int j = 0; j < 3; ++j) {
            u64 pij = mul2(xx[i], yy[j]);
#pragma unroll
            for (int k = 0; k < 3; ++k)
                enc[i * 9 + j * 3 + k] = mul2(pij, zz[k]);
        }
    }

    // ---- h1 = relu(G1 @ enc) [32]: even rows from constant, odd from SMEM ----
    u64 h1[32];
#pragma unroll
    for (int c = 0; c < 32; ++c) {
        int base = OFF_G1 + 27 * c;
        u64 s;
        if (c & 1) {
            s = mul2(SP(sPack, base), enc[0]);
#pragma unroll
            for (int j = 1; j < 27; ++j)
                s = fma2(SP(sPack, base + j), enc[j], s);
        } else {
            s = mul2(CP(base), enc[0]);
#pragma unroll
            for (int j = 1; j < 27; ++j)
                s = fma2(CP(base + j), enc[j], s);
        }
        h1[c] = relu2(s);
    }

    // ---- load x channels (8B coalesced, voxel pair contiguous) ----
    u64 xr[32];
#pragma unroll
    for (int c = 0; c < 32; ++c)
        xr[c] = xb[(size_t)c * HPAIR];

    // ---- fused G2/G3/output: out = sum_k relu(G2[k]·h1) * (G3t[k]·x) ----
    // G2 weights via constant port (LDCU/UR), G3t via SMEM port (LDS/GPR):
    // the two load streams use independent ports and register pools.
    u64 acc = 0ull;   // packed (0.0f, 0.0f)
#pragma unroll 8
    for (int k = 0; k < 64; ++k) {
        int ba = OFF_G2 + 32 * k;
        int bb = OFF_G3 + 32 * k;
        u64 s2 = mul2(CP(ba), h1[0]);
        u64 t  = mul2(SP(sPack, bb), xr[0]);
#pragma unroll
        for (int c = 1; c < 32; ++c) {
            s2 = fma2(CP(ba + c), h1[c], s2);
            t  = fma2(SP(sPack, bb + c), xr[c], t);
        }
        acc = fma2(relu2(s2), t, acc);
    }

    out2[q] = acc;
}

extern "C" void kernel_launch(void* const* d_in, const int* in_sizes, int n_in,
                              void* d_out, int out_size)
{
    const float* x     = (const float*)d_in[0];
    const float* d_all = (const float*)d_in[1];

    // 1) duplicate/reorder weights into device scratch (single small block)
    pack_weights_kernel<<<1, 256>>>((const float*)d_in[2], (const float*)d_in[3],
                                    (const float*)d_in[4], (const float*)d_in[5],
                                    (const float*)d_in[6]);

    // 2) move scratch into constant bank (D2D memcpy node — graph-capturable)
    void* psrc = nullptr;
    cudaGetSymbolAddress(&psrc, g_packbuf);
    cudaMemcpyToSymbolAsync(cPack, psrc, sizeof(float2) * NPACK, 0,
                            cudaMemcpyDeviceToDevice, 0);

    // 3) main fused kernel, 2 voxels per thread (128 thr, 2 CTA/SM)
    int npairs  = out_size / 2;        // 884,736
    int threads = 128;
    int blocks  = (npairs + threads - 1) / threads;
    fused_filter2_kernel<<<blocks, threads>>>((const u64*)x, (const u64*)d_all,
                                              (u64*)d_out, npairs);
}